// round 7
// baseline (speedup 1.0000x reference)
#include <cuda_runtime.h>
#include <cuda_bf16.h>
#include <cstdint>

// PaiNN conv: ds (N,64), dv (N,3,64) concatenated in d_out.
// Inputs: 0 node(N,64) 1 equivariant(N,3,64) 2 rbf(E,20) 3 envelope(E,1)
//         4 r_ij(E,3) 5 edge_index(E,2) i64/i32  6 Ws(64,64) 7 bs(64)
//         8 Wphi(192,64) 9 bphi(192) 10 Ww(192,20) 11 bw(192)

#define U 64
#define S3 192
#define R 20
#define MAXN 50000
#define MAXE 800000
#define EROW 28          // floats per edge record (112B)
#define MT 64            // nodes per MLP tile

typedef unsigned long long ull;

__device__ float g_s[(size_t)MAXN * S3];
__device__ float g_sw[(size_t)MAXE * S3];
__device__ float g_edata[(size_t)MAXE * EROW];
__device__ int   g_idx_is64;
__device__ int   g_cnt[MAXN];
__device__ int   g_scan[MAXN];
__device__ int   g_bsum[64];
__device__ int   g_off[MAXN + 1];
__device__ int   g_run[MAXN];

// ---------------- packed f32x2 helpers ----------------
__device__ __forceinline__ ull pk2(float lo, float hi) {
    ull r;
    asm("mov.b64 %0, {%1, %2};" : "=l"(r) : "f"(lo), "f"(hi));
    return r;
}
__device__ __forceinline__ ull fma2(ull a, ull b, ull c) {
    ull d;
    asm("fma.rn.f32x2 %0, %1, %2, %3;" : "=l"(d) : "l"(a), "l"(b), "l"(c));
    return d;
}
__device__ __forceinline__ void upk(ull a, float& lo, float& hi) {
    asm("mov.b64 {%0, %1}, %2;" : "=f"(lo), "=f"(hi) : "l"(a));
}
__device__ __forceinline__ float upk_sum(ull a) {
    float lo, hi;
    upk(a, lo, hi);
    return lo + hi;
}

// ---------------- idx dtype detector ----------------
__global__ void detect_idx_kernel(const int* __restrict__ eidx32, int n_edges) {
    __shared__ int warp_or[8];
    int v = 0;
    int limit = n_edges < 4096 ? n_edges : 4096;
    for (int k = threadIdx.x; k < limit; k += blockDim.x)
        v |= eidx32[2 * k + 1];
    for (int o = 16; o > 0; o >>= 1)
        v |= __shfl_xor_sync(0xffffffffu, v, o);
    if ((threadIdx.x & 31) == 0) warp_or[threadIdx.x >> 5] = v;
    __syncthreads();
    if (threadIdx.x == 0) {
        int r = 0;
        for (int w = 0; w < (int)(blockDim.x >> 5); w++) r |= warp_or[w];
        g_idx_is64 = (r == 0) ? 1 : 0;
    }
}

__global__ void zero_cnt_kernel(int n_nodes) {
    int i = blockIdx.x * blockDim.x + threadIdx.x;
    if (i < n_nodes) g_cnt[i] = 0;
}

__global__ void hist_kernel(const void* __restrict__ eidx, int n_edges) {
    const bool is64 = (g_idx_is64 != 0);
    for (int e = blockIdx.x * blockDim.x + threadIdx.x; e < n_edges;
         e += gridDim.x * blockDim.x) {
        int dst = is64 ? (int)((const long long*)eidx)[2 * (size_t)e]
                       : ((const int*)eidx)[2 * (size_t)e];
        atomicAdd(&g_cnt[dst], 1);
    }
}

__global__ void scan1_kernel(int n_nodes) {
    __shared__ int sh[1024];
    int tid = threadIdx.x;
    int i = blockIdx.x * 1024 + tid;
    int v = (i < n_nodes) ? g_cnt[i] : 0;
    sh[tid] = v;
    __syncthreads();
    for (int off = 1; off < 1024; off <<= 1) {
        int t = (tid >= off) ? sh[tid - off] : 0;
        __syncthreads();
        sh[tid] += t;
        __syncthreads();
    }
    if (i < n_nodes) g_scan[i] = sh[tid] - v;
    if (tid == 1023) g_bsum[blockIdx.x] = sh[1023];
}

// parallel block-sum exclusive scan (nb <= 64)
__global__ void scan2_kernel(int nb) {
    __shared__ int sh[64];
    int t = threadIdx.x;
    int v = (t < nb) ? g_bsum[t] : 0;
    sh[t] = v;
    __syncthreads();
    for (int off = 1; off < 64; off <<= 1) {
        int u = (t >= off) ? sh[t - off] : 0;
        __syncthreads();
        sh[t] += u;
        __syncthreads();
    }
    if (t < nb) g_bsum[t] = sh[t] - v;  // exclusive
}

__global__ void scan3_kernel(int n_nodes, int n_edges) {
    int i = blockIdx.x * blockDim.x + threadIdx.x;
    if (i < n_nodes) {
        int off = g_scan[i] + g_bsum[i >> 10];
        g_off[i] = off;
        g_run[i] = off;
    }
    if (i == 0) g_off[n_nodes] = n_edges;
}

// ---------------- scatter: build 112B edge records in dst-sorted order ----
__global__ void scatter_kernel(const void* __restrict__ eidx,
                               const float* __restrict__ rbf,
                               const float* __restrict__ env,
                               const float* __restrict__ rij,
                               int n_edges) {
    const bool is64 = (g_idx_is64 != 0);
    for (int e = blockIdx.x * blockDim.x + threadIdx.x; e < n_edges;
         e += gridDim.x * blockDim.x) {
        int dst, j;
        if (is64) {
            const long long* p = (const long long*)eidx;
            dst = (int)p[2 * (size_t)e];
            j = (int)p[2 * (size_t)e + 1];
        } else {
            const int* p = (const int*)eidx;
            dst = p[2 * (size_t)e];
            j = p[2 * (size_t)e + 1];
        }
        int pos = atomicAdd(&g_run[dst], 1);
        float4* row = (float4*)(g_edata + (size_t)pos * EROW);
        float4 a;
        a.x = __int_as_float(j);
        a.y = __int_as_float(dst);
        a.z = env[e];
        a.w = 0.f;
        const float4* rb = (const float4*)(rbf + (size_t)e * R);
        float4 r0 = rb[0], r1 = rb[1], r2 = rb[2], r3 = rb[3], r4 = rb[4];
        float4 b;
        b.x = rij[3 * (size_t)e];
        b.y = rij[3 * (size_t)e + 1];
        b.z = rij[3 * (size_t)e + 2];
        b.w = 0.f;
        row[0] = a; row[1] = r0; row[2] = r1; row[3] = r2;
        row[4] = r3; row[5] = r4; row[6] = b;
    }
}

// ---------------- register-tiled node MLP (proven: 89us) ----------------
#define SMEM_MLP ((64 * 68 + 64 * 196 + 192 + 64 * 66 + 64 * 66) * 4)

__global__ void __launch_bounds__(256)
mlp_kernel(const float* __restrict__ node,
           const float* __restrict__ Ws, const float* __restrict__ bs,
           const float* __restrict__ Wphi, const float* __restrict__ bphi,
           int n_nodes) {
    extern __shared__ float sh[];
    float* sWsT  = sh;
    float* sWpT  = sWsT + 64 * 68;
    float* sbphi = sWpT + 64 * 196;
    float* snT   = sbphi + 192;
    float* shhT  = snT + 64 * 66;

    const int tid = threadIdx.x;

    for (int x = tid; x < 64 * 64; x += 256) {
        int cc = x >> 6, k = x & 63;
        sWsT[k * 68 + cc] = Ws[x];
    }
    for (int x = tid; x < 192 * 64; x += 256) {
        int cc = x >> 6, k = x & 63;
        sWpT[k * 196 + cc] = Wphi[x];
    }
    for (int x = tid; x < 192; x += 256) sbphi[x] = bphi[x];

    const int n0 = blockIdx.x * MT;
    for (int x = tid; x < MT * 64; x += 256) {
        int n = x >> 6, k = x & 63;
        snT[k * 66 + n] = (n0 + n < n_nodes) ? node[(size_t)(n0 + n) * 64 + k] : 0.f;
    }
    __syncthreads();

    const int cq = tid & 15, nq = tid >> 4;
    const int cc0 = cq * 4, nn0 = nq * 4;

    {
        ull acc[4][2];
#pragma unroll
        for (int ci = 0; ci < 4; ci++) {
            float b = bs[cc0 + ci];
            acc[ci][0] = pk2(b, b);
            acc[ci][1] = pk2(b, b);
        }
#pragma unroll 8
        for (int k = 0; k < 64; k++) {
            float4 wv = *(const float4*)&sWsT[k * 68 + cc0];
            ull np0 = *(const ull*)&snT[k * 66 + nn0];
            ull np1 = *(const ull*)&snT[k * 66 + nn0 + 2];
            ull w;
            w = pk2(wv.x, wv.x); acc[0][0] = fma2(np0, w, acc[0][0]); acc[0][1] = fma2(np1, w, acc[0][1]);
            w = pk2(wv.y, wv.y); acc[1][0] = fma2(np0, w, acc[1][0]); acc[1][1] = fma2(np1, w, acc[1][1]);
            w = pk2(wv.z, wv.z); acc[2][0] = fma2(np0, w, acc[2][0]); acc[2][1] = fma2(np1, w, acc[2][1]);
            w = pk2(wv.w, wv.w); acc[3][0] = fma2(np0, w, acc[3][0]); acc[3][1] = fma2(np1, w, acc[3][1]);
        }
#pragma unroll
        for (int ci = 0; ci < 4; ci++) {
            float h0, h1, h2, h3;
            upk(acc[ci][0], h0, h1);
            upk(acc[ci][1], h2, h3);
            h0 *= 1.f / (1.f + __expf(-h0));
            h1 *= 1.f / (1.f + __expf(-h1));
            h2 *= 1.f / (1.f + __expf(-h2));
            h3 *= 1.f / (1.f + __expf(-h3));
            *(ull*)&shhT[(cc0 + ci) * 66 + nn0]     = pk2(h0, h1);
            *(ull*)&shhT[(cc0 + ci) * 66 + nn0 + 2] = pk2(h2, h3);
        }
    }
    __syncthreads();

    for (int p = 0; p < 3; p++) {
        ull acc[4][2];
#pragma unroll
        for (int ci = 0; ci < 4; ci++) {
            float b = sbphi[p * 64 + cc0 + ci];
            acc[ci][0] = pk2(b, b);
            acc[ci][1] = pk2(b, b);
        }
#pragma unroll 8
        for (int k = 0; k < 64; k++) {
            float4 wv = *(const float4*)&sWpT[k * 196 + p * 64 + cc0];
            ull np0 = *(const ull*)&shhT[k * 66 + nn0];
            ull np1 = *(const ull*)&shhT[k * 66 + nn0 + 2];
            ull w;
            w = pk2(wv.x, wv.x); acc[0][0] = fma2(np0, w, acc[0][0]); acc[0][1] = fma2(np1, w, acc[0][1]);
            w = pk2(wv.y, wv.y); acc[1][0] = fma2(np0, w, acc[1][0]); acc[1][1] = fma2(np1, w, acc[1][1]);
            w = pk2(wv.z, wv.z); acc[2][0] = fma2(np0, w, acc[2][0]); acc[2][1] = fma2(np1, w, acc[2][1]);
            w = pk2(wv.w, wv.w); acc[3][0] = fma2(np0, w, acc[3][0]); acc[3][1] = fma2(np1, w, acc[3][1]);
        }
        float sv[4][4];
#pragma unroll
        for (int ci = 0; ci < 4; ci++) {
            upk(acc[ci][0], sv[ci][0], sv[ci][1]);
            upk(acc[ci][1], sv[ci][2], sv[ci][3]);
        }
#pragma unroll
        for (int ni = 0; ni < 4; ni++) {
            int n = n0 + nn0 + ni;
            if (n < n_nodes) {
                float4 v = make_float4(sv[0][ni], sv[1][ni], sv[2][ni], sv[3][ni]);
                *(float4*)&g_s[(size_t)n * S3 + p * 64 + cc0] = v;
            }
        }
    }
}

// ---------------- sw kernel: edge-parallel, barrier-free ----------------
// 192 threads, thread c owns radial channel c (weights in regs).
// Streams dst-sorted records (linear broadcast reads), coalesced g_s gather,
// coalesced g_sw write. No shared memory, no __syncthreads.
__global__ void __launch_bounds__(192)
sw_kernel(const float* __restrict__ Ww, const float* __restrict__ bw,
          int n_edges) {
    const int c = threadIdx.x;

    ull wwp[10];
    const float* wr = Ww + (size_t)c * R;
#pragma unroll
    for (int k = 0; k < 10; k++) wwp[k] = pk2(wr[2 * k], wr[2 * k + 1]);
    const float bwv = bw[c];

    const int begin = (int)(((long long)n_edges * blockIdx.x) / gridDim.x);
    const int endv  = (int)(((long long)n_edges * (blockIdx.x + 1)) / gridDim.x);

#pragma unroll 4
    for (int pos = begin; pos < endv; pos++) {
        const float* row = g_edata + (size_t)pos * EROW;
        int j = __float_as_int(row[0]);
        float en = row[2];
        float s = g_s[(size_t)j * S3 + c];          // coalesced gather
        const ulonglong2* rb = (const ulonglong2*)(row + 4);  // 16B-aligned
        ull a0 = pk2(bwv, 0.f);
        ull a1 = pk2(0.f, 0.f);
#pragma unroll
        for (int q = 0; q < 5; q++) {
            ulonglong2 t = rb[q];                   // broadcast LDG.128
            a0 = fma2(t.x, wwp[2 * q],     a0);
            a1 = fma2(t.y, wwp[2 * q + 1], a1);
        }
        float w = (upk_sum(a0) + upk_sum(a1)) * en;
        g_sw[(size_t)pos * S3 + c] = s * w;         // coalesced write
    }
}

// ---------------- out kernel: node-parallel, barrier-free ----------------
// 256 threads = 4 nodes x 64 channels. Thread owns (node, ch) with 4 register
// accumulators; per edge: 3 streaming sw reads + 3 equiv gathers + broadcasts.
// Every output element written -> no zeroing pass needed.
__global__ void __launch_bounds__(256)
out_kernel(const float* __restrict__ equiv,
           float* __restrict__ out_ds, float* __restrict__ out_dv,
           int n_nodes) {
    const int nq = threadIdx.x >> 6;
    const int ch = threadIdx.x & 63;

    for (int ibase = blockIdx.x * 4; ibase < n_nodes; ibase += gridDim.x * 4) {
        int i = ibase + nq;
        if (i >= n_nodes) continue;
        int start = g_off[i], end = g_off[i + 1];

        float ds = 0.f, d0 = 0.f, d1 = 0.f, d2 = 0.f;

#pragma unroll 2
        for (int pos = start; pos < end; pos++) {
            const float* row = g_edata + (size_t)pos * EROW;
            int j = __float_as_int(row[0]);          // broadcast
            const float* swp = g_sw + (size_t)pos * S3 + ch;
            float sw0 = swp[0], sw1 = swp[64], sw2 = swp[128];  // streaming
            const float* vp = equiv + (size_t)j * S3 + ch;
            float v0 = vp[0], v1 = vp[64], v2 = vp[128];        // gather
            float r0 = row[24], r1 = row[25], r2 = row[26];     // broadcast
            ds += sw0;
            d0 = fmaf(v0, sw1, fmaf(r0, sw2, d0));
            d1 = fmaf(v1, sw1, fmaf(r1, sw2, d1));
            d2 = fmaf(v2, sw1, fmaf(r2, sw2, d2));
        }

        out_ds[(size_t)i * U + ch] = ds;
        out_dv[((size_t)i * 3 + 0) * U + ch] = d0;
        out_dv[((size_t)i * 3 + 1) * U + ch] = d1;
        out_dv[((size_t)i * 3 + 2) * U + ch] = d2;
    }
}

// ---------------------------------------------------------------------------
extern "C" void kernel_launch(void* const* d_in, const int* in_sizes, int n_in,
                              void* d_out, int out_size) {
    const float* node  = (const float*)d_in[0];
    const float* equiv = (const float*)d_in[1];
    const float* rbf   = (const float*)d_in[2];
    const float* env   = (const float*)d_in[3];
    const float* rij   = (const float*)d_in[4];
    const void*  eidx  = d_in[5];
    const float* Ws    = (const float*)d_in[6];
    const float* bs    = (const float*)d_in[7];
    const float* Wphi  = (const float*)d_in[8];
    const float* bphi  = (const float*)d_in[9];
    const float* Ww    = (const float*)d_in[10];
    const float* bw    = (const float*)d_in[11];

    int n_nodes = in_sizes[0] / U;
    int n_edges = in_sizes[3];

    float* out_ds = (float*)d_out;
    float* out_dv = out_ds + (size_t)n_nodes * U;

    int nb_scan = (n_nodes + 1023) / 1024;

    detect_idx_kernel<<<1, 256>>>((const int*)eidx, n_edges);
    zero_cnt_kernel<<<(n_nodes + 255) / 256, 256>>>(n_nodes);

    cudaFuncSetAttribute(mlp_kernel, cudaFuncAttributeMaxDynamicSharedMemorySize, SMEM_MLP);
    mlp_kernel<<<(n_nodes + MT - 1) / MT, 256, SMEM_MLP>>>(node, Ws, bs, Wphi, bphi, n_nodes);

    hist_kernel<<<400, 256>>>(eidx, n_edges);
    scan1_kernel<<<nb_scan, 1024>>>(n_nodes);
    scan2_kernel<<<1, 64>>>(nb_scan);
    scan3_kernel<<<(n_nodes + 1023) / 1024, 1024>>>(n_nodes, n_edges);
    scatter_kernel<<<400, 256>>>(eidx, rbf, env, rij, n_edges);

    sw_kernel<<<1184, 192>>>(Ww, bw, n_edges);
    out_kernel<<<(n_nodes + 3) / 4, 256>>>(equiv, out_ds, out_dv, n_nodes);
}

// round 8
// speedup vs baseline: 1.5763x; 1.5763x over previous
#include <cuda_runtime.h>
#include <cuda_bf16.h>
#include <cstdint>

// PaiNN conv: ds (N,64), dv (N,3,64) concatenated in d_out.
// Inputs: 0 node(N,64) 1 equivariant(N,3,64) 2 rbf(E,20) 3 envelope(E,1)
//         4 r_ij(E,3) 5 edge_index(E,2) i64/i32  6 Ws(64,64) 7 bs(64)
//         8 Wphi(192,64) 9 bphi(192) 10 Ww(192,20) 11 bw(192)

#define U 64
#define S3 192
#define R 20
#define MAXN 50000
#define MAXE 800000
#define CE 48            // edges per tile
#define EROW 28          // floats per edge record (112B)
#define NB 592
#define MT 64            // nodes per MLP tile

typedef unsigned long long ull;

__device__ float g_s[(size_t)MAXN * S3];
__device__ float g_edata[(size_t)MAXE * EROW];
__device__ int   g_idx_is64;
__device__ int   g_cnt[MAXN];
__device__ int   g_scan[MAXN];
__device__ int   g_bsum[64];
__device__ int   g_run[MAXN];

// ---------------- packed f32x2 helpers ----------------
__device__ __forceinline__ ull pk2(float lo, float hi) {
    ull r;
    asm("mov.b64 %0, {%1, %2};" : "=l"(r) : "f"(lo), "f"(hi));
    return r;
}
__device__ __forceinline__ ull fma2(ull a, ull b, ull c) {
    ull d;
    asm("fma.rn.f32x2 %0, %1, %2, %3;" : "=l"(d) : "l"(a), "l"(b), "l"(c));
    return d;
}
__device__ __forceinline__ void upk(ull a, float& lo, float& hi) {
    asm("mov.b64 {%0, %1}, %2;" : "=f"(lo), "=f"(hi) : "l"(a));
}
__device__ __forceinline__ float upk_sum(ull a) {
    float lo, hi;
    upk(a, lo, hi);
    return lo + hi;
}
__device__ __forceinline__ void red_add(float* p, float v) {
    asm volatile("red.global.add.f32 [%0], %1;" :: "l"(p), "f"(v) : "memory");
}

// ---------------- idx dtype detector ----------------
__global__ void detect_idx_kernel(const int* __restrict__ eidx32, int n_edges) {
    __shared__ int warp_or[8];
    int v = 0;
    int limit = n_edges < 4096 ? n_edges : 4096;
    for (int k = threadIdx.x; k < limit; k += blockDim.x)
        v |= eidx32[2 * k + 1];
    for (int o = 16; o > 0; o >>= 1)
        v |= __shfl_xor_sync(0xffffffffu, v, o);
    if ((threadIdx.x & 31) == 0) warp_or[threadIdx.x >> 5] = v;
    __syncthreads();
    if (threadIdx.x == 0) {
        int r = 0;
        for (int w = 0; w < (int)(blockDim.x >> 5); w++) r |= warp_or[w];
        g_idx_is64 = (r == 0) ? 1 : 0;
    }
}

__global__ void zero_cnt_kernel(int n_nodes) {
    int i = blockIdx.x * blockDim.x + threadIdx.x;
    if (i < n_nodes) g_cnt[i] = 0;
}

__global__ void zero_out_kernel(float* __restrict__ out, long long n) {
    long long n4 = n >> 2;
    float4 z = make_float4(0.f, 0.f, 0.f, 0.f);
    float4* o4 = (float4*)out;
    for (long long i = (long long)blockIdx.x * blockDim.x + threadIdx.x; i < n4;
         i += (long long)gridDim.x * blockDim.x)
        o4[i] = z;
    long long base = n4 << 2;
    for (long long i = base + (long long)blockIdx.x * blockDim.x + threadIdx.x; i < n;
         i += (long long)gridDim.x * blockDim.x)
        out[i] = 0.f;
}

__global__ void hist_kernel(const void* __restrict__ eidx, int n_edges) {
    const bool is64 = (g_idx_is64 != 0);
    for (int e = blockIdx.x * blockDim.x + threadIdx.x; e < n_edges;
         e += gridDim.x * blockDim.x) {
        int dst = is64 ? (int)((const long long*)eidx)[2 * (size_t)e]
                       : ((const int*)eidx)[2 * (size_t)e];
        atomicAdd(&g_cnt[dst], 1);
    }
}

__global__ void scan1_kernel(int n_nodes) {
    __shared__ int sh[1024];
    int tid = threadIdx.x;
    int i = blockIdx.x * 1024 + tid;
    int v = (i < n_nodes) ? g_cnt[i] : 0;
    sh[tid] = v;
    __syncthreads();
    for (int off = 1; off < 1024; off <<= 1) {
        int t = (tid >= off) ? sh[tid - off] : 0;
        __syncthreads();
        sh[tid] += t;
        __syncthreads();
    }
    if (i < n_nodes) g_scan[i] = sh[tid] - v;
    if (tid == 1023) g_bsum[blockIdx.x] = sh[1023];
}

// parallel block-sum exclusive scan (nb <= 64)
__global__ void scan2_kernel(int nb) {
    __shared__ int sh[64];
    int t = threadIdx.x;
    int v = (t < nb) ? g_bsum[t] : 0;
    sh[t] = v;
    __syncthreads();
    for (int off = 1; off < 64; off <<= 1) {
        int u = (t >= off) ? sh[t - off] : 0;
        __syncthreads();
        sh[t] += u;
        __syncthreads();
    }
    if (t < nb) g_bsum[t] = sh[t] - v;  // exclusive
}

__global__ void scan3_kernel(int n_nodes) {
    int i = blockIdx.x * blockDim.x + threadIdx.x;
    if (i < n_nodes)
        g_run[i] = g_scan[i] + g_bsum[i >> 10];
}

// ---------------- scatter: build 112B edge records in dst-sorted order ----
__global__ void scatter_kernel(const void* __restrict__ eidx,
                               const float* __restrict__ rbf,
                               const float* __restrict__ env,
                               const float* __restrict__ rij,
                               int n_edges) {
    const bool is64 = (g_idx_is64 != 0);
    for (int e = blockIdx.x * blockDim.x + threadIdx.x; e < n_edges;
         e += gridDim.x * blockDim.x) {
        int dst, j;
        if (is64) {
            const long long* p = (const long long*)eidx;
            dst = (int)p[2 * (size_t)e];
            j = (int)p[2 * (size_t)e + 1];
        } else {
            const int* p = (const int*)eidx;
            dst = p[2 * (size_t)e];
            j = p[2 * (size_t)e + 1];
        }
        int pos = atomicAdd(&g_run[dst], 1);
        float4* row = (float4*)(g_edata + (size_t)pos * EROW);
        float4 a;
        a.x = __int_as_float(j);
        a.y = __int_as_float(dst);
        a.z = env[e];
        a.w = 0.f;
        const float4* rb = (const float4*)(rbf + (size_t)e * R);
        float4 r0 = rb[0], r1 = rb[1], r2 = rb[2], r3 = rb[3], r4 = rb[4];
        float4 b;
        b.x = rij[3 * (size_t)e];
        b.y = rij[3 * (size_t)e + 1];
        b.z = rij[3 * (size_t)e + 2];
        b.w = 0.f;
        row[0] = a; row[1] = r0; row[2] = r1; row[3] = r2;
        row[4] = r3; row[5] = r4; row[6] = b;
    }
}

// ---------------- register-tiled node MLP (proven: 89us) ----------------
#define SMEM_MLP ((64 * 68 + 64 * 196 + 192 + 64 * 66 + 64 * 66) * 4)

__global__ void __launch_bounds__(256)
mlp_kernel(const float* __restrict__ node,
           const float* __restrict__ Ws, const float* __restrict__ bs,
           const float* __restrict__ Wphi, const float* __restrict__ bphi,
           int n_nodes) {
    extern __shared__ float sh[];
    float* sWsT  = sh;
    float* sWpT  = sWsT + 64 * 68;
    float* sbphi = sWpT + 64 * 196;
    float* snT   = sbphi + 192;
    float* shhT  = snT + 64 * 66;

    const int tid = threadIdx.x;

    for (int x = tid; x < 64 * 64; x += 256) {
        int cc = x >> 6, k = x & 63;
        sWsT[k * 68 + cc] = Ws[x];
    }
    for (int x = tid; x < 192 * 64; x += 256) {
        int cc = x >> 6, k = x & 63;
        sWpT[k * 196 + cc] = Wphi[x];
    }
    for (int x = tid; x < 192; x += 256) sbphi[x] = bphi[x];

    const int n0 = blockIdx.x * MT;
    for (int x = tid; x < MT * 64; x += 256) {
        int n = x >> 6, k = x & 63;
        snT[k * 66 + n] = (n0 + n < n_nodes) ? node[(size_t)(n0 + n) * 64 + k] : 0.f;
    }
    __syncthreads();

    const int cq = tid & 15, nq = tid >> 4;
    const int cc0 = cq * 4, nn0 = nq * 4;

    {
        ull acc[4][2];
#pragma unroll
        for (int ci = 0; ci < 4; ci++) {
            float b = bs[cc0 + ci];
            acc[ci][0] = pk2(b, b);
            acc[ci][1] = pk2(b, b);
        }
#pragma unroll 8
        for (int k = 0; k < 64; k++) {
            float4 wv = *(const float4*)&sWsT[k * 68 + cc0];
            ull np0 = *(const ull*)&snT[k * 66 + nn0];
            ull np1 = *(const ull*)&snT[k * 66 + nn0 + 2];
            ull w;
            w = pk2(wv.x, wv.x); acc[0][0] = fma2(np0, w, acc[0][0]); acc[0][1] = fma2(np1, w, acc[0][1]);
            w = pk2(wv.y, wv.y); acc[1][0] = fma2(np0, w, acc[1][0]); acc[1][1] = fma2(np1, w, acc[1][1]);
            w = pk2(wv.z, wv.z); acc[2][0] = fma2(np0, w, acc[2][0]); acc[2][1] = fma2(np1, w, acc[2][1]);
            w = pk2(wv.w, wv.w); acc[3][0] = fma2(np0, w, acc[3][0]); acc[3][1] = fma2(np1, w, acc[3][1]);
        }
#pragma unroll
        for (int ci = 0; ci < 4; ci++) {
            float h0, h1, h2, h3;
            upk(acc[ci][0], h0, h1);
            upk(acc[ci][1], h2, h3);
            h0 *= 1.f / (1.f + __expf(-h0));
            h1 *= 1.f / (1.f + __expf(-h1));
            h2 *= 1.f / (1.f + __expf(-h2));
            h3 *= 1.f / (1.f + __expf(-h3));
            *(ull*)&shhT[(cc0 + ci) * 66 + nn0]     = pk2(h0, h1);
            *(ull*)&shhT[(cc0 + ci) * 66 + nn0 + 2] = pk2(h2, h3);
        }
    }
    __syncthreads();

    for (int p = 0; p < 3; p++) {
        ull acc[4][2];
#pragma unroll
        for (int ci = 0; ci < 4; ci++) {
            float b = sbphi[p * 64 + cc0 + ci];
            acc[ci][0] = pk2(b, b);
            acc[ci][1] = pk2(b, b);
        }
#pragma unroll 8
        for (int k = 0; k < 64; k++) {
            float4 wv = *(const float4*)&sWpT[k * 196 + p * 64 + cc0];
            ull np0 = *(const ull*)&shhT[k * 66 + nn0];
            ull np1 = *(const ull*)&shhT[k * 66 + nn0 + 2];
            ull w;
            w = pk2(wv.x, wv.x); acc[0][0] = fma2(np0, w, acc[0][0]); acc[0][1] = fma2(np1, w, acc[0][1]);
            w = pk2(wv.y, wv.y); acc[1][0] = fma2(np0, w, acc[1][0]); acc[1][1] = fma2(np1, w, acc[1][1]);
            w = pk2(wv.z, wv.z); acc[2][0] = fma2(np0, w, acc[2][0]); acc[2][1] = fma2(np1, w, acc[2][1]);
            w = pk2(wv.w, wv.w); acc[3][0] = fma2(np0, w, acc[3][0]); acc[3][1] = fma2(np1, w, acc[3][1]);
        }
        float sv[4][4];
#pragma unroll
        for (int ci = 0; ci < 4; ci++) {
            upk(acc[ci][0], sv[ci][0], sv[ci][1]);
            upk(acc[ci][1], sv[ci][2], sv[ci][3]);
        }
#pragma unroll
        for (int ni = 0; ni < 4; ni++) {
            int n = n0 + nn0 + ni;
            if (n < n_nodes) {
                float4 v = make_float4(sv[0][ni], sv[1][ni], sv[2][ni], sv[3][ni]);
                *(float4*)&g_s[(size_t)n * S3 + p * 64 + cc0] = v;
            }
        }
    }
}

// ---------------- sweep: dst-sorted ranges, CE=48, 8-deep gather batches ---
// 256 threads. Phase B: thread c<192 owns radial channel c (weights in regs),
// gathers batched 8-deep into registers before the dot products.
// Phase C: thread = output element, run-carry accumulator, equiv gathers
// batched 8-deep. Records double-buffered via register prefetch.
__global__ void __launch_bounds__(256)
sweep_kernel(const float* __restrict__ Ww, const float* __restrict__ bw,
             const float* __restrict__ equiv,
             float* __restrict__ out_ds, float* __restrict__ out_dv,
             int n_edges) {
    __shared__ __align__(16) float sh_ed[2][CE * EROW];
    __shared__ __align__(16) float sh_sw[CE][S3];

    const int tid  = threadIdx.x;
    const int ch   = tid & 63;
    const int comp = tid >> 6;   // 0..3
    const int c    = tid;        // radial channel if < 192
    const int d    = comp - 1;

    ull wwp[10];
    float bwv = 0.f;
    if (c < S3) {
        const float* wr = Ww + (size_t)c * R;
#pragma unroll
        for (int k = 0; k < 10; k++) wwp[k] = pk2(wr[2 * k], wr[2 * k + 1]);
        bwv = bw[c];
    }

    const int begin = (int)(((long long)n_edges * blockIdx.x) / gridDim.x);
    const int bend  = (int)(((long long)n_edges * (blockIdx.x + 1)) / gridDim.x);
    const int nt    = (bend - begin + CE - 1) / CE;
    const int NF4   = CE * EROW / 4;   // 336 float4 per tile

    int   cur = -1;
    float acc = 0.f;

    // prologue: stage tile 0
    {
        int cnt0 = min(CE, bend - begin);
        for (int x = tid; x < cnt0 * (EROW / 4); x += 256) {
            float4 v = *(const float4*)(g_edata + (size_t)begin * EROW + x * 4);
            *(float4*)&sh_ed[0][x * 4] = v;
        }
    }
    __syncthreads();

    for (int ti = 0; ti < nt; ti++) {
        const int tb  = begin + ti * CE;
        const int cnt = min(CE, bend - tb);
        const int buf = ti & 1;

        // prefetch next tile into registers (linear addresses, no deps)
        float4 pre0, pre1;
        bool hp0 = false, hp1 = false;
        if (ti + 1 < nt) {
            int nb2 = tb + CE;
            int cnt2 = min(CE, bend - nb2);
            int lim = cnt2 * (EROW / 4);
            if (tid < lim) {
                pre0 = *(const float4*)(g_edata + (size_t)nb2 * EROW + tid * 4);
                hp0 = true;
            }
            if (tid + 256 < lim) {
                pre1 = *(const float4*)(g_edata + (size_t)nb2 * EROW + (tid + 256) * 4);
                hp1 = true;
            }
        }

        // phase B: sw[el][c] = s[j][c] * ((rbf . Ww_c + bw_c) * env)
        if (c < S3) {
            for (int e0 = 0; e0 < cnt; e0 += 8) {
                const int m = min(8, cnt - e0);
                float sv[8];
#pragma unroll
                for (int u = 0; u < 8; u++) {
                    if (u < m) {
                        int j = __float_as_int(sh_ed[buf][(e0 + u) * EROW]);
                        sv[u] = g_s[(size_t)j * S3 + c];   // 8 gathers in flight
                    }
                }
#pragma unroll
                for (int u = 0; u < 8; u++) {
                    if (u < m) {
                        const float* row = &sh_ed[buf][(e0 + u) * EROW];
                        const ulonglong2* rb = (const ulonglong2*)(row + 4);
                        ull a0 = pk2(bwv, 0.f);
                        ull a1 = pk2(0.f, 0.f);
#pragma unroll
                        for (int q = 0; q < 5; q++) {
                            ulonglong2 t = rb[q];
                            a0 = fma2(t.x, wwp[2 * q],     a0);
                            a1 = fma2(t.y, wwp[2 * q + 1], a1);
                        }
                        float w = (upk_sum(a0) + upk_sum(a1)) * row[2];
                        sh_sw[e0 + u][c] = sv[u] * w;
                    }
                }
            }
        }
        __syncthreads();

        // phase C: run-carry segmented accumulation
        if (comp == 0) {
#pragma unroll 4
            for (int el = 0; el < cnt; el++) {
                const float* row = &sh_ed[buf][el * EROW];
                int ni = __float_as_int(row[1]);
                if (ni != cur) {
                    if (cur >= 0) red_add(out_ds + (size_t)cur * U + ch, acc);
                    acc = 0.f;
                    cur = ni;
                }
                acc += sh_sw[el][ch];
            }
        } else {
            for (int e0 = 0; e0 < cnt; e0 += 8) {
                const int m = min(8, cnt - e0);
                float vj[8];
#pragma unroll
                for (int u = 0; u < 8; u++) {
                    if (u < m) {
                        int j = __float_as_int(sh_ed[buf][(e0 + u) * EROW]);
                        vj[u] = equiv[((size_t)j * 3 + d) * U + ch];  // 8 in flight
                    }
                }
#pragma unroll
                for (int u = 0; u < 8; u++) {
                    if (u < m) {
                        const float* row = &sh_ed[buf][(e0 + u) * EROW];
                        int ni = __float_as_int(row[1]);
                        if (ni != cur) {
                            if (cur >= 0)
                                red_add(out_dv + ((size_t)cur * 3 + d) * U + ch, acc);
                            acc = 0.f;
                            cur = ni;
                        }
                        acc = fmaf(vj[u], sh_sw[e0 + u][64 + ch],
                                   fmaf(row[24 + d], sh_sw[e0 + u][128 + ch], acc));
                    }
                }
            }
        }

        // store prefetched tile into the other buffer
        if (hp0) *(float4*)&sh_ed[buf ^ 1][tid * 4] = pre0;
        if (hp1) *(float4*)&sh_ed[buf ^ 1][(tid + 256) * 4] = pre1;
        __syncthreads();
    }

    // final flush
    if (cur >= 0) {
        if (comp == 0) red_add(out_ds + (size_t)cur * U + ch, acc);
        else           red_add(out_dv + ((size_t)cur * 3 + d) * U + ch, acc);
    }
}

// ---------------------------------------------------------------------------
extern "C" void kernel_launch(void* const* d_in, const int* in_sizes, int n_in,
                              void* d_out, int out_size) {
    const float* node  = (const float*)d_in[0];
    const float* equiv = (const float*)d_in[1];
    const float* rbf   = (const float*)d_in[2];
    const float* env   = (const float*)d_in[3];
    const float* rij   = (const float*)d_in[4];
    const void*  eidx  = d_in[5];
    const float* Ws    = (const float*)d_in[6];
    const float* bs    = (const float*)d_in[7];
    const float* Wphi  = (const float*)d_in[8];
    const float* bphi  = (const float*)d_in[9];
    const float* Ww    = (const float*)d_in[10];
    const float* bw    = (const float*)d_in[11];

    int n_nodes = in_sizes[0] / U;
    int n_edges = in_sizes[3];

    float* out_ds = (float*)d_out;
    float* out_dv = out_ds + (size_t)n_nodes * U;

    int nb_scan = (n_nodes + 1023) / 1024;

    detect_idx_kernel<<<1, 256>>>((const int*)eidx, n_edges);
    zero_cnt_kernel<<<(n_nodes + 255) / 256, 256>>>(n_nodes);
    zero_out_kernel<<<592, 256>>>((float*)d_out, (long long)out_size);

    cudaFuncSetAttribute(mlp_kernel, cudaFuncAttributeMaxDynamicSharedMemorySize, SMEM_MLP);
    mlp_kernel<<<(n_nodes + MT - 1) / MT, 256, SMEM_MLP>>>(node, Ws, bs, Wphi, bphi, n_nodes);

    hist_kernel<<<400, 256>>>(eidx, n_edges);
    scan1_kernel<<<nb_scan, 1024>>>(n_nodes);
    scan2_kernel<<<1, 64>>>(nb_scan);
    scan3_kernel<<<(n_nodes + 1023) / 1024, 1024>>>(n_nodes);
    scatter_kernel<<<400, 256>>>(eidx, rbf, env, rij, n_edges);

    sweep_kernel<<<NB, 256>>>(Ww, bw, equiv, out_ds, out_dv, n_edges);
}

// round 9
// speedup vs baseline: 1.9193x; 1.2176x over previous
#include <cuda_runtime.h>
#include <cuda_bf16.h>
#include <cstdint>

// PaiNN conv: ds (N,64), dv (N,3,64) concatenated in d_out.
// Inputs: 0 node(N,64) 1 equivariant(N,3,64) 2 rbf(E,20) 3 envelope(E,1)
//         4 r_ij(E,3) 5 edge_index(E,2) i64/i32  6 Ws(64,64) 7 bs(64)
//         8 Wphi(192,64) 9 bphi(192) 10 Ww(192,20) 11 bw(192)

#define U 64
#define S3 192
#define R 20
#define MAXN 50000
#define MAXE 800000
#define EROW 28          // floats per edge record (112B)
#define MT 64            // nodes per MLP tile
#define NGRP 1184        // sweep groups (64 threads each) = 2368 warps = 1 wave

typedef unsigned long long ull;

__device__ float g_s[(size_t)MAXN * S3];
__device__ float g_edata[(size_t)MAXE * EROW];
__device__ int   g_idx_is64;
__device__ int   g_cnt[MAXN];
__device__ int   g_scan[MAXN];
__device__ int   g_bsum[64];
__device__ int   g_run[MAXN];

// ---------------- packed f32x2 helpers ----------------
__device__ __forceinline__ ull pk2(float lo, float hi) {
    ull r;
    asm("mov.b64 %0, {%1, %2};" : "=l"(r) : "f"(lo), "f"(hi));
    return r;
}
__device__ __forceinline__ ull fma2(ull a, ull b, ull c) {
    ull d;
    asm("fma.rn.f32x2 %0, %1, %2, %3;" : "=l"(d) : "l"(a), "l"(b), "l"(c));
    return d;
}
__device__ __forceinline__ void upk(ull a, float& lo, float& hi) {
    asm("mov.b64 {%0, %1}, %2;" : "=f"(lo), "=f"(hi) : "l"(a));
}
__device__ __forceinline__ float upk_sum(ull a) {
    float lo, hi;
    upk(a, lo, hi);
    return lo + hi;
}
__device__ __forceinline__ void red_add(float* p, float v) {
    asm volatile("red.global.add.f32 [%0], %1;" :: "l"(p), "f"(v) : "memory");
}

// ---------------- idx dtype detector ----------------
__global__ void detect_idx_kernel(const int* __restrict__ eidx32, int n_edges) {
    __shared__ int warp_or[8];
    int v = 0;
    int limit = n_edges < 4096 ? n_edges : 4096;
    for (int k = threadIdx.x; k < limit; k += blockDim.x)
        v |= eidx32[2 * k + 1];
    for (int o = 16; o > 0; o >>= 1)
        v |= __shfl_xor_sync(0xffffffffu, v, o);
    if ((threadIdx.x & 31) == 0) warp_or[threadIdx.x >> 5] = v;
    __syncthreads();
    if (threadIdx.x == 0) {
        int r = 0;
        for (int w = 0; w < (int)(blockDim.x >> 5); w++) r |= warp_or[w];
        g_idx_is64 = (r == 0) ? 1 : 0;
    }
}

__global__ void zero_cnt_kernel(int n_nodes) {
    int i = blockIdx.x * blockDim.x + threadIdx.x;
    if (i < n_nodes) g_cnt[i] = 0;
}

__global__ void zero_out_kernel(float* __restrict__ out, long long n) {
    long long n4 = n >> 2;
    float4 z = make_float4(0.f, 0.f, 0.f, 0.f);
    float4* o4 = (float4*)out;
    for (long long i = (long long)blockIdx.x * blockDim.x + threadIdx.x; i < n4;
         i += (long long)gridDim.x * blockDim.x)
        o4[i] = z;
    long long base = n4 << 2;
    for (long long i = base + (long long)blockIdx.x * blockDim.x + threadIdx.x; i < n;
         i += (long long)gridDim.x * blockDim.x)
        out[i] = 0.f;
}

__global__ void hist_kernel(const void* __restrict__ eidx, int n_edges) {
    const bool is64 = (g_idx_is64 != 0);
    for (int e = blockIdx.x * blockDim.x + threadIdx.x; e < n_edges;
         e += gridDim.x * blockDim.x) {
        int dst = is64 ? (int)((const long long*)eidx)[2 * (size_t)e]
                       : ((const int*)eidx)[2 * (size_t)e];
        atomicAdd(&g_cnt[dst], 1);
    }
}

__global__ void scan1_kernel(int n_nodes) {
    __shared__ int sh[1024];
    int tid = threadIdx.x;
    int i = blockIdx.x * 1024 + tid;
    int v = (i < n_nodes) ? g_cnt[i] : 0;
    sh[tid] = v;
    __syncthreads();
    for (int off = 1; off < 1024; off <<= 1) {
        int t = (tid >= off) ? sh[tid - off] : 0;
        __syncthreads();
        sh[tid] += t;
        __syncthreads();
    }
    if (i < n_nodes) g_scan[i] = sh[tid] - v;
    if (tid == 1023) g_bsum[blockIdx.x] = sh[1023];
}

// parallel block-sum exclusive scan (nb <= 64)
__global__ void scan2_kernel(int nb) {
    __shared__ int sh[64];
    int t = threadIdx.x;
    int v = (t < nb) ? g_bsum[t] : 0;
    sh[t] = v;
    __syncthreads();
    for (int off = 1; off < 64; off <<= 1) {
        int u = (t >= off) ? sh[t - off] : 0;
        __syncthreads();
        sh[t] += u;
        __syncthreads();
    }
    if (t < nb) g_bsum[t] = sh[t] - v;  // exclusive
}

__global__ void scan3_kernel(int n_nodes) {
    int i = blockIdx.x * blockDim.x + threadIdx.x;
    if (i < n_nodes)
        g_run[i] = g_scan[i] + g_bsum[i >> 10];
}

// ---------------- scatter: build 112B edge records in dst-sorted order ----
__global__ void scatter_kernel(const void* __restrict__ eidx,
                               const float* __restrict__ rbf,
                               const float* __restrict__ env,
                               const float* __restrict__ rij,
                               int n_edges) {
    const bool is64 = (g_idx_is64 != 0);
    for (int e = blockIdx.x * blockDim.x + threadIdx.x; e < n_edges;
         e += gridDim.x * blockDim.x) {
        int dst, j;
        if (is64) {
            const long long* p = (const long long*)eidx;
            dst = (int)p[2 * (size_t)e];
            j = (int)p[2 * (size_t)e + 1];
        } else {
            const int* p = (const int*)eidx;
            dst = p[2 * (size_t)e];
            j = p[2 * (size_t)e + 1];
        }
        int pos = atomicAdd(&g_run[dst], 1);
        float4* row = (float4*)(g_edata + (size_t)pos * EROW);
        float4 a;
        a.x = __int_as_float(j);
        a.y = __int_as_float(dst);
        a.z = env[e];
        a.w = 0.f;
        const float4* rb = (const float4*)(rbf + (size_t)e * R);
        float4 r0 = rb[0], r1 = rb[1], r2 = rb[2], r3 = rb[3], r4 = rb[4];
        float4 b;
        b.x = rij[3 * (size_t)e];
        b.y = rij[3 * (size_t)e + 1];
        b.z = rij[3 * (size_t)e + 2];
        b.w = 0.f;
        row[0] = a; row[1] = r0; row[2] = r1; row[3] = r2;
        row[4] = r3; row[5] = r4; row[6] = b;
    }
}

// ---------------- register-tiled node MLP (proven: 89us) ----------------
#define SMEM_MLP ((64 * 68 + 64 * 196 + 192 + 64 * 66 + 64 * 66) * 4)

__global__ void __launch_bounds__(256)
mlp_kernel(const float* __restrict__ node,
           const float* __restrict__ Ws, const float* __restrict__ bs,
           const float* __restrict__ Wphi, const float* __restrict__ bphi,
           int n_nodes) {
    extern __shared__ float sh[];
    float* sWsT  = sh;
    float* sWpT  = sWsT + 64 * 68;
    float* sbphi = sWpT + 64 * 196;
    float* snT   = sbphi + 192;
    float* shhT  = snT + 64 * 66;

    const int tid = threadIdx.x;

    for (int x = tid; x < 64 * 64; x += 256) {
        int cc = x >> 6, k = x & 63;
        sWsT[k * 68 + cc] = Ws[x];
    }
    for (int x = tid; x < 192 * 64; x += 256) {
        int cc = x >> 6, k = x & 63;
        sWpT[k * 196 + cc] = Wphi[x];
    }
    for (int x = tid; x < 192; x += 256) sbphi[x] = bphi[x];

    const int n0 = blockIdx.x * MT;
    for (int x = tid; x < MT * 64; x += 256) {
        int n = x >> 6, k = x & 63;
        snT[k * 66 + n] = (n0 + n < n_nodes) ? node[(size_t)(n0 + n) * 64 + k] : 0.f;
    }
    __syncthreads();

    const int cq = tid & 15, nq = tid >> 4;
    const int cc0 = cq * 4, nn0 = nq * 4;

    {
        ull acc[4][2];
#pragma unroll
        for (int ci = 0; ci < 4; ci++) {
            float b = bs[cc0 + ci];
            acc[ci][0] = pk2(b, b);
            acc[ci][1] = pk2(b, b);
        }
#pragma unroll 8
        for (int k = 0; k < 64; k++) {
            float4 wv = *(const float4*)&sWsT[k * 68 + cc0];
            ull np0 = *(const ull*)&snT[k * 66 + nn0];
            ull np1 = *(const ull*)&snT[k * 66 + nn0 + 2];
            ull w;
            w = pk2(wv.x, wv.x); acc[0][0] = fma2(np0, w, acc[0][0]); acc[0][1] = fma2(np1, w, acc[0][1]);
            w = pk2(wv.y, wv.y); acc[1][0] = fma2(np0, w, acc[1][0]); acc[1][1] = fma2(np1, w, acc[1][1]);
            w = pk2(wv.z, wv.z); acc[2][0] = fma2(np0, w, acc[2][0]); acc[2][1] = fma2(np1, w, acc[2][1]);
            w = pk2(wv.w, wv.w); acc[3][0] = fma2(np0, w, acc[3][0]); acc[3][1] = fma2(np1, w, acc[3][1]);
        }
#pragma unroll
        for (int ci = 0; ci < 4; ci++) {
            float h0, h1, h2, h3;
            upk(acc[ci][0], h0, h1);
            upk(acc[ci][1], h2, h3);
            h0 *= 1.f / (1.f + __expf(-h0));
            h1 *= 1.f / (1.f + __expf(-h1));
            h2 *= 1.f / (1.f + __expf(-h2));
            h3 *= 1.f / (1.f + __expf(-h3));
            *(ull*)&shhT[(cc0 + ci) * 66 + nn0]     = pk2(h0, h1);
            *(ull*)&shhT[(cc0 + ci) * 66 + nn0 + 2] = pk2(h2, h3);
        }
    }
    __syncthreads();

    for (int p = 0; p < 3; p++) {
        ull acc[4][2];
#pragma unroll
        for (int ci = 0; ci < 4; ci++) {
            float b = sbphi[p * 64 + cc0 + ci];
            acc[ci][0] = pk2(b, b);
            acc[ci][1] = pk2(b, b);
        }
#pragma unroll 8
        for (int k = 0; k < 64; k++) {
            float4 wv = *(const float4*)&sWpT[k * 196 + p * 64 + cc0];
            ull np0 = *(const ull*)&shhT[k * 66 + nn0];
            ull np1 = *(const ull*)&shhT[k * 66 + nn0 + 2];
            ull w;
            w = pk2(wv.x, wv.x); acc[0][0] = fma2(np0, w, acc[0][0]); acc[0][1] = fma2(np1, w, acc[0][1]);
            w = pk2(wv.y, wv.y); acc[1][0] = fma2(np0, w, acc[1][0]); acc[1][1] = fma2(np1, w, acc[1][1]);
            w = pk2(wv.z, wv.z); acc[2][0] = fma2(np0, w, acc[2][0]); acc[2][1] = fma2(np1, w, acc[2][1]);
            w = pk2(wv.w, wv.w); acc[3][0] = fma2(np0, w, acc[3][0]); acc[3][1] = fma2(np1, w, acc[3][1]);
        }
        float sv[4][4];
#pragma unroll
        for (int ci = 0; ci < 4; ci++) {
            upk(acc[ci][0], sv[ci][0], sv[ci][1]);
            upk(acc[ci][1], sv[ci][2], sv[ci][3]);
        }
#pragma unroll
        for (int ni = 0; ni < 4; ni++) {
            int n = n0 + nn0 + ni;
            if (n < n_nodes) {
                float4 v = make_float4(sv[0][ni], sv[1][ni], sv[2][ni], sv[3][ni]);
                *(float4*)&g_s[(size_t)n * S3 + p * 64 + cc0] = v;
            }
        }
    }
}

// ---------------- sweep: barrier-free, lane-local, 64-thread groups -------
// Group = 64 threads (2 independent warps) sweeping a contiguous dst-sorted
// edge range. Thread t owns radial channels {t, 64+t, 128+t} (weights in 60
// regs) AND output elements ds[t], dv[0..2][t] — phase C is lane-local:
// no shared memory, no __syncthreads, no shuffles anywhere.
__global__ void __launch_bounds__(128, 4)
sweep_kernel(const float* __restrict__ Ww, const float* __restrict__ bw,
             const float* __restrict__ equiv,
             float* __restrict__ out_ds, float* __restrict__ out_dv,
             int n_edges) {
    const int grp = blockIdx.x * 2 + (threadIdx.x >> 6);   // group id
    const int t   = threadIdx.x & 63;                      // channel 0..63

    // weights for channels t, 64+t, 128+t (rows are 80B -> 8B-aligned ull)
    ull wwp[3][10];
    float bwv[3];
#pragma unroll
    for (int g = 0; g < 3; g++) {
        const float* wr = Ww + (size_t)(g * 64 + t) * R;
#pragma unroll
        for (int k = 0; k < 10; k++)
            wwp[g][k] = *(const ull*)&wr[2 * k];
        bwv[g] = bw[g * 64 + t];
    }

    const int begin = (int)(((long long)n_edges * grp) / NGRP);
    const int end   = (int)(((long long)n_edges * (grp + 1)) / NGRP);

    int   cur = -1;
    float a0 = 0.f, a1 = 0.f, a2 = 0.f, a3 = 0.f;

#pragma unroll 2
    for (int pos = begin; pos < end; pos++) {
        const float* row = g_edata + (size_t)pos * EROW;
        float4 hdr = *(const float4*)row;            // j, dst, env (broadcast)
        int   j  = __float_as_int(hdr.x);
        int   ni = __float_as_int(hdr.y);
        float en = hdr.z;

        // issue all 6 gathers up front (coalesced 128B per warp)
        const float* sp = g_s + (size_t)j * S3 + t;
        float s0 = sp[0], s1 = sp[64], s2 = sp[128];
        const float* vp = equiv + (size_t)j * S3 + t;
        float v0 = vp[0], v1 = vp[64], v2 = vp[128];
        float4 rj = *(const float4*)(row + 24);      // rij (broadcast)

        // 3 radial dots, k-pair packed (broadcast ull loads from record)
        const ull* rb = (const ull*)(row + 4);
        float w[3];
#pragma unroll
        for (int g = 0; g < 3; g++) {
            ull pa = pk2(bwv[g], 0.f);
            ull pb = pk2(0.f, 0.f);
#pragma unroll
            for (int q = 0; q < 5; q++) {
                pa = fma2(rb[2 * q],     wwp[g][2 * q],     pa);
                pb = fma2(rb[2 * q + 1], wwp[g][2 * q + 1], pb);
            }
            w[g] = (upk_sum(pa) + upk_sum(pb)) * en;
        }

        float sw0 = s0 * w[0];
        float sw1 = s1 * w[1];
        float sw2 = s2 * w[2];

        if (ni != cur) {
            if (cur >= 0) {
                red_add(out_ds + (size_t)cur * U + t, a0);
                float* dv = out_dv + (size_t)cur * S3 + t;
                red_add(dv,       a1);
                red_add(dv + 64,  a2);
                red_add(dv + 128, a3);
            }
            a0 = a1 = a2 = a3 = 0.f;
            cur = ni;
        }

        a0 += sw0;
        a1 = fmaf(v0, sw1, fmaf(rj.x, sw2, a1));
        a2 = fmaf(v1, sw1, fmaf(rj.y, sw2, a2));
        a3 = fmaf(v2, sw1, fmaf(rj.z, sw2, a3));
    }

    if (cur >= 0) {
        red_add(out_ds + (size_t)cur * U + t, a0);
        float* dv = out_dv + (size_t)cur * S3 + t;
        red_add(dv,       a1);
        red_add(dv + 64,  a2);
        red_add(dv + 128, a3);
    }
}

// ---------------------------------------------------------------------------
extern "C" void kernel_launch(void* const* d_in, const int* in_sizes, int n_in,
                              void* d_out, int out_size) {
    const float* node  = (const float*)d_in[0];
    const float* equiv = (const float*)d_in[1];
    const float* rbf   = (const float*)d_in[2];
    const float* env   = (const float*)d_in[3];
    const float* rij   = (const float*)d_in[4];
    const void*  eidx  = d_in[5];
    const float* Ws    = (const float*)d_in[6];
    const float* bs    = (const float*)d_in[7];
    const float* Wphi  = (const float*)d_in[8];
    const float* bphi  = (const float*)d_in[9];
    const float* Ww    = (const float*)d_in[10];
    const float* bw    = (const float*)d_in[11];

    int n_nodes = in_sizes[0] / U;
    int n_edges = in_sizes[3];

    float* out_ds = (float*)d_out;
    float* out_dv = out_ds + (size_t)n_nodes * U;

    int nb_scan = (n_nodes + 1023) / 1024;

    detect_idx_kernel<<<1, 256>>>((const int*)eidx, n_edges);
    zero_cnt_kernel<<<(n_nodes + 255) / 256, 256>>>(n_nodes);
    zero_out_kernel<<<592, 256>>>((float*)d_out, (long long)out_size);

    cudaFuncSetAttribute(mlp_kernel, cudaFuncAttributeMaxDynamicSharedMemorySize, SMEM_MLP);
    mlp_kernel<<<(n_nodes + MT - 1) / MT, 256, SMEM_MLP>>>(node, Ws, bs, Wphi, bphi, n_nodes);

    hist_kernel<<<400, 256>>>(eidx, n_edges);
    scan1_kernel<<<nb_scan, 1024>>>(n_nodes);
    scan2_kernel<<<1, 64>>>(nb_scan);
    scan3_kernel<<<(n_nodes + 1023) / 1024, 1024>>>(n_nodes);
    scatter_kernel<<<400, 256>>>(eidx, rbf, env, rij, n_edges);

    sweep_kernel<<<NGRP / 2, 128>>>(Ww, bw, equiv, out_ds, out_dv, n_edges);
}

// round 10
// speedup vs baseline: 2.2822x; 1.1891x over previous
#include <cuda_runtime.h>
#include <cuda_bf16.h>
#include <cstdint>

// PaiNN conv: ds (N,64), dv (N,3,64) concatenated in d_out.
// Inputs: 0 node(N,64) 1 equivariant(N,3,64) 2 rbf(E,20) 3 envelope(E,1)
//         4 r_ij(E,3) 5 edge_index(E,2) i64/i32  6 Ws(64,64) 7 bs(64)
//         8 Wphi(192,64) 9 bphi(192) 10 Ww(192,20) 11 bw(192)

#define U 64
#define S3 192
#define R 20
#define MAXN 50000
#define MAXE 800000
#define EROW 28          // floats per edge record (112B)
#define MT 64            // nodes per MLP tile
#define NGRP 1184        // sweep groups (64 threads each) = 2368 warps = 1 wave

typedef unsigned long long ull;

__device__ float g_s[(size_t)MAXN * S3];
__device__ float g_edata[(size_t)MAXE * EROW];
__device__ int   g_idx_is64;
__device__ int   g_cnt[MAXN];
__device__ int   g_scan[MAXN];
__device__ int   g_bsum[64];
__device__ int   g_run[MAXN];

// ---------------- packed f32x2 helpers ----------------
__device__ __forceinline__ ull pk2(float lo, float hi) {
    ull r;
    asm("mov.b64 %0, {%1, %2};" : "=l"(r) : "f"(lo), "f"(hi));
    return r;
}
__device__ __forceinline__ ull fma2(ull a, ull b, ull c) {
    ull d;
    asm("fma.rn.f32x2 %0, %1, %2, %3;" : "=l"(d) : "l"(a), "l"(b), "l"(c));
    return d;
}
__device__ __forceinline__ void upk(ull a, float& lo, float& hi) {
    asm("mov.b64 {%0, %1}, %2;" : "=f"(lo), "=f"(hi) : "l"(a));
}
__device__ __forceinline__ float upk_sum(ull a) {
    float lo, hi;
    upk(a, lo, hi);
    return lo + hi;
}
__device__ __forceinline__ void red_add(float* p, float v) {
    asm volatile("red.global.add.f32 [%0], %1;" :: "l"(p), "f"(v) : "memory");
}

// ---------------- idx dtype detector ----------------
__global__ void detect_idx_kernel(const int* __restrict__ eidx32, int n_edges) {
    __shared__ int warp_or[8];
    int v = 0;
    int limit = n_edges < 4096 ? n_edges : 4096;
    for (int k = threadIdx.x; k < limit; k += blockDim.x)
        v |= eidx32[2 * k + 1];
    for (int o = 16; o > 0; o >>= 1)
        v |= __shfl_xor_sync(0xffffffffu, v, o);
    if ((threadIdx.x & 31) == 0) warp_or[threadIdx.x >> 5] = v;
    __syncthreads();
    if (threadIdx.x == 0) {
        int r = 0;
        for (int w = 0; w < (int)(blockDim.x >> 5); w++) r |= warp_or[w];
        g_idx_is64 = (r == 0) ? 1 : 0;
    }
}

__global__ void zero_cnt_kernel(int n_nodes) {
    int i = blockIdx.x * blockDim.x + threadIdx.x;
    if (i < n_nodes) g_cnt[i] = 0;
}

__global__ void zero_out_kernel(float* __restrict__ out, long long n) {
    long long n4 = n >> 2;
    float4 z = make_float4(0.f, 0.f, 0.f, 0.f);
    float4* o4 = (float4*)out;
    for (long long i = (long long)blockIdx.x * blockDim.x + threadIdx.x; i < n4;
         i += (long long)gridDim.x * blockDim.x)
        o4[i] = z;
    long long base = n4 << 2;
    for (long long i = base + (long long)blockIdx.x * blockDim.x + threadIdx.x; i < n;
         i += (long long)gridDim.x * blockDim.x)
        out[i] = 0.f;
}

__global__ void hist_kernel(const void* __restrict__ eidx, int n_edges) {
    const bool is64 = (g_idx_is64 != 0);
    for (int e = blockIdx.x * blockDim.x + threadIdx.x; e < n_edges;
         e += gridDim.x * blockDim.x) {
        int dst = is64 ? (int)((const long long*)eidx)[2 * (size_t)e]
                       : ((const int*)eidx)[2 * (size_t)e];
        atomicAdd(&g_cnt[dst], 1);
    }
}

__global__ void scan1_kernel(int n_nodes) {
    __shared__ int sh[1024];
    int tid = threadIdx.x;
    int i = blockIdx.x * 1024 + tid;
    int v = (i < n_nodes) ? g_cnt[i] : 0;
    sh[tid] = v;
    __syncthreads();
    for (int off = 1; off < 1024; off <<= 1) {
        int t = (tid >= off) ? sh[tid - off] : 0;
        __syncthreads();
        sh[tid] += t;
        __syncthreads();
    }
    if (i < n_nodes) g_scan[i] = sh[tid] - v;
    if (tid == 1023) g_bsum[blockIdx.x] = sh[1023];
}

// parallel block-sum exclusive scan (nb <= 64)
__global__ void scan2_kernel(int nb) {
    __shared__ int sh[64];
    int t = threadIdx.x;
    int v = (t < nb) ? g_bsum[t] : 0;
    sh[t] = v;
    __syncthreads();
    for (int off = 1; off < 64; off <<= 1) {
        int u = (t >= off) ? sh[t - off] : 0;
        __syncthreads();
        sh[t] += u;
        __syncthreads();
    }
    if (t < nb) g_bsum[t] = sh[t] - v;  // exclusive
}

__global__ void scan3_kernel(int n_nodes) {
    int i = blockIdx.x * blockDim.x + threadIdx.x;
    if (i < n_nodes)
        g_run[i] = g_scan[i] + g_bsum[i >> 10];
}

// ---------------- scatter: build 112B edge records in dst-sorted order ----
__global__ void scatter_kernel(const void* __restrict__ eidx,
                               const float* __restrict__ rbf,
                               const float* __restrict__ env,
                               const float* __restrict__ rij,
                               int n_edges) {
    const bool is64 = (g_idx_is64 != 0);
    for (int e = blockIdx.x * blockDim.x + threadIdx.x; e < n_edges;
         e += gridDim.x * blockDim.x) {
        int dst, j;
        if (is64) {
            const long long* p = (const long long*)eidx;
            dst = (int)p[2 * (size_t)e];
            j = (int)p[2 * (size_t)e + 1];
        } else {
            const int* p = (const int*)eidx;
            dst = p[2 * (size_t)e];
            j = p[2 * (size_t)e + 1];
        }
        int pos = atomicAdd(&g_run[dst], 1);
        float4* row = (float4*)(g_edata + (size_t)pos * EROW);
        float4 a;
        a.x = __int_as_float(j);
        a.y = __int_as_float(dst);
        a.z = env[e];
        a.w = 0.f;
        const float4* rb = (const float4*)(rbf + (size_t)e * R);
        float4 r0 = rb[0], r1 = rb[1], r2 = rb[2], r3 = rb[3], r4 = rb[4];
        float4 b;
        b.x = rij[3 * (size_t)e];
        b.y = rij[3 * (size_t)e + 1];
        b.z = rij[3 * (size_t)e + 2];
        b.w = 0.f;
        row[0] = a; row[1] = r0; row[2] = r1; row[3] = r2;
        row[4] = r3; row[5] = r4; row[6] = b;
    }
}

// ---------------- register-tiled node MLP (proven: 89us) ----------------
#define SMEM_MLP ((64 * 68 + 64 * 196 + 192 + 64 * 66 + 64 * 66) * 4)

__global__ void __launch_bounds__(256)
mlp_kernel(const float* __restrict__ node,
           const float* __restrict__ Ws, const float* __restrict__ bs,
           const float* __restrict__ Wphi, const float* __restrict__ bphi,
           int n_nodes) {
    extern __shared__ float sh[];
    float* sWsT  = sh;
    float* sWpT  = sWsT + 64 * 68;
    float* sbphi = sWpT + 64 * 196;
    float* snT   = sbphi + 192;
    float* shhT  = snT + 64 * 66;

    const int tid = threadIdx.x;

    for (int x = tid; x < 64 * 64; x += 256) {
        int cc = x >> 6, k = x & 63;
        sWsT[k * 68 + cc] = Ws[x];
    }
    for (int x = tid; x < 192 * 64; x += 256) {
        int cc = x >> 6, k = x & 63;
        sWpT[k * 196 + cc] = Wphi[x];
    }
    for (int x = tid; x < 192; x += 256) sbphi[x] = bphi[x];

    const int n0 = blockIdx.x * MT;
    for (int x = tid; x < MT * 64; x += 256) {
        int n = x >> 6, k = x & 63;
        snT[k * 66 + n] = (n0 + n < n_nodes) ? node[(size_t)(n0 + n) * 64 + k] : 0.f;
    }
    __syncthreads();

    const int cq = tid & 15, nq = tid >> 4;
    const int cc0 = cq * 4, nn0 = nq * 4;

    {
        ull acc[4][2];
#pragma unroll
        for (int ci = 0; ci < 4; ci++) {
            float b = bs[cc0 + ci];
            acc[ci][0] = pk2(b, b);
            acc[ci][1] = pk2(b, b);
        }
#pragma unroll 8
        for (int k = 0; k < 64; k++) {
            float4 wv = *(const float4*)&sWsT[k * 68 + cc0];
            ull np0 = *(const ull*)&snT[k * 66 + nn0];
            ull np1 = *(const ull*)&snT[k * 66 + nn0 + 2];
            ull w;
            w = pk2(wv.x, wv.x); acc[0][0] = fma2(np0, w, acc[0][0]); acc[0][1] = fma2(np1, w, acc[0][1]);
            w = pk2(wv.y, wv.y); acc[1][0] = fma2(np0, w, acc[1][0]); acc[1][1] = fma2(np1, w, acc[1][1]);
            w = pk2(wv.z, wv.z); acc[2][0] = fma2(np0, w, acc[2][0]); acc[2][1] = fma2(np1, w, acc[2][1]);
            w = pk2(wv.w, wv.w); acc[3][0] = fma2(np0, w, acc[3][0]); acc[3][1] = fma2(np1, w, acc[3][1]);
        }
#pragma unroll
        for (int ci = 0; ci < 4; ci++) {
            float h0, h1, h2, h3;
            upk(acc[ci][0], h0, h1);
            upk(acc[ci][1], h2, h3);
            h0 *= 1.f / (1.f + __expf(-h0));
            h1 *= 1.f / (1.f + __expf(-h1));
            h2 *= 1.f / (1.f + __expf(-h2));
            h3 *= 1.f / (1.f + __expf(-h3));
            *(ull*)&shhT[(cc0 + ci) * 66 + nn0]     = pk2(h0, h1);
            *(ull*)&shhT[(cc0 + ci) * 66 + nn0 + 2] = pk2(h2, h3);
        }
    }
    __syncthreads();

    for (int p = 0; p < 3; p++) {
        ull acc[4][2];
#pragma unroll
        for (int ci = 0; ci < 4; ci++) {
            float b = sbphi[p * 64 + cc0 + ci];
            acc[ci][0] = pk2(b, b);
            acc[ci][1] = pk2(b, b);
        }
#pragma unroll 8
        for (int k = 0; k < 64; k++) {
            float4 wv = *(const float4*)&sWpT[k * 196 + p * 64 + cc0];
            ull np0 = *(const ull*)&shhT[k * 66 + nn0];
            ull np1 = *(const ull*)&shhT[k * 66 + nn0 + 2];
            ull w;
            w = pk2(wv.x, wv.x); acc[0][0] = fma2(np0, w, acc[0][0]); acc[0][1] = fma2(np1, w, acc[0][1]);
            w = pk2(wv.y, wv.y); acc[1][0] = fma2(np0, w, acc[1][0]); acc[1][1] = fma2(np1, w, acc[1][1]);
            w = pk2(wv.z, wv.z); acc[2][0] = fma2(np0, w, acc[2][0]); acc[2][1] = fma2(np1, w, acc[2][1]);
            w = pk2(wv.w, wv.w); acc[3][0] = fma2(np0, w, acc[3][0]); acc[3][1] = fma2(np1, w, acc[3][1]);
        }
        float sv[4][4];
#pragma unroll
        for (int ci = 0; ci < 4; ci++) {
            upk(acc[ci][0], sv[ci][0], sv[ci][1]);
            upk(acc[ci][1], sv[ci][2], sv[ci][3]);
        }
#pragma unroll
        for (int ni = 0; ni < 4; ni++) {
            int n = n0 + nn0 + ni;
            if (n < n_nodes) {
                float4 v = make_float4(sv[0][ni], sv[1][ni], sv[2][ni], sv[3][ni]);
                *(float4*)&g_s[(size_t)n * S3 + p * 64 + cc0] = v;
            }
        }
    }
}

// ---------------- sweep: barrier-free lane-local + 3-stage SW pipeline ----
// Group = 64 threads (2 warps) sweeping a contiguous dst-sorted range.
// Thread t owns radial channels {t,64+t,128+t} AND outputs ds[t],dv[*][t].
// Pipeline per iteration for edge pos:
//   A: load header(pos+2)  (linear address, no deps)
//   B: issue 6 gathers for pos+1 (header loaded 2 iters ago -> latency hidden)
//   C: compute pos (gathers issued last iter; rbf/rij re-read, L1-hot line)
__global__ void __launch_bounds__(128, 4)
sweep_kernel(const float* __restrict__ Ww, const float* __restrict__ bw,
             const float* __restrict__ equiv,
             float* __restrict__ out_ds, float* __restrict__ out_dv,
             int n_edges) {
    const int grp = blockIdx.x * 2 + (threadIdx.x >> 6);   // group id
    const int t   = threadIdx.x & 63;                      // channel 0..63

    ull wwp[3][10];
    float bwv[3];
#pragma unroll
    for (int g = 0; g < 3; g++) {
        const float* wr = Ww + (size_t)(g * 64 + t) * R;
#pragma unroll
        for (int k = 0; k < 10; k++)
            wwp[g][k] = *(const ull*)&wr[2 * k];
        bwv[g] = bw[g * 64 + t];
    }

    const int begin = (int)(((long long)n_edges * grp) / NGRP);
    const int end   = (int)(((long long)n_edges * (grp + 1)) / NGRP);

    int   cur = -1;
    float a0 = 0.f, a1 = 0.f, a2 = 0.f, a3 = 0.f;

    // pipeline state
    int   niA = 0, niB = 0, jB = 0;
    float enA = 0.f, enB = 0.f;
    float s0 = 0.f, s1 = 0.f, s2 = 0.f, v0 = 0.f, v1 = 0.f, v2 = 0.f;

    if (begin < end) {
        // prologue: header(begin) + its gathers (one-time dependent chain)
        float4 h = *(const float4*)(g_edata + (size_t)begin * EROW);
        int jA = __float_as_int(h.x);
        niA = __float_as_int(h.y);
        enA = h.z;
        const float* sp = g_s + (size_t)jA * S3 + t;
        s0 = sp[0]; s1 = sp[64]; s2 = sp[128];
        const float* vp = equiv + (size_t)jA * S3 + t;
        v0 = vp[0]; v1 = vp[64]; v2 = vp[128];
        if (begin + 1 < end) {
            float4 h2 = *(const float4*)(g_edata + (size_t)(begin + 1) * EROW);
            jB  = __float_as_int(h2.x);
            niB = __float_as_int(h2.y);
            enB = h2.z;
        }
    }

    for (int pos = begin; pos < end; pos++) {
        // stage A: header(pos+2) — linear, independent, issues immediately
        int jC = 0, niC = 0;
        float enC = 0.f;
        if (pos + 2 < end) {
            float4 h = *(const float4*)(g_edata + (size_t)(pos + 2) * EROW);
            jC  = __float_as_int(h.x);
            niC = __float_as_int(h.y);
            enC = h.z;
        }

        // stage B: gathers for pos+1 (header available since last iter)
        float s0N = 0.f, s1N = 0.f, s2N = 0.f, v0N = 0.f, v1N = 0.f, v2N = 0.f;
        if (pos + 1 < end) {
            const float* spN = g_s + (size_t)jB * S3 + t;
            s0N = spN[0]; s1N = spN[64]; s2N = spN[128];
            const float* vpN = equiv + (size_t)jB * S3 + t;
            v0N = vpN[0]; v1N = vpN[64]; v2N = vpN[128];
        }

        // stage C: compute pos (rbf/rij from record line — L1-hot)
        const float* row = g_edata + (size_t)pos * EROW;
        const ull* rb = (const ull*)(row + 4);
        float4 rj = *(const float4*)(row + 24);
        float w[3];
#pragma unroll
        for (int g = 0; g < 3; g++) {
            ull pa = pk2(bwv[g], 0.f);
            ull pb = pk2(0.f, 0.f);
#pragma unroll
            for (int q = 0; q < 5; q++) {
                pa = fma2(rb[2 * q],     wwp[g][2 * q],     pa);
                pb = fma2(rb[2 * q + 1], wwp[g][2 * q + 1], pb);
            }
            w[g] = (upk_sum(pa) + upk_sum(pb)) * enA;
        }

        float sw0 = s0 * w[0];
        float sw1 = s1 * w[1];
        float sw2 = s2 * w[2];

        if (niA != cur) {
            if (cur >= 0) {
                red_add(out_ds + (size_t)cur * U + t, a0);
                float* dv = out_dv + (size_t)cur * S3 + t;
                red_add(dv,       a1);
                red_add(dv + 64,  a2);
                red_add(dv + 128, a3);
            }
            a0 = a1 = a2 = a3 = 0.f;
            cur = niA;
        }

        a0 += sw0;
        a1 = fmaf(v0, sw1, fmaf(rj.x, sw2, a1));
        a2 = fmaf(v1, sw1, fmaf(rj.y, sw2, a2));
        a3 = fmaf(v2, sw1, fmaf(rj.z, sw2, a3));

        // rotate pipeline state
        niA = niB; enA = enB;
        jB = jC; niB = niC; enB = enC;
        s0 = s0N; s1 = s1N; s2 = s2N;
        v0 = v0N; v1 = v1N; v2 = v2N;
    }

    if (cur >= 0) {
        red_add(out_ds + (size_t)cur * U + t, a0);
        float* dv = out_dv + (size_t)cur * S3 + t;
        red_add(dv,       a1);
        red_add(dv + 64,  a2);
        red_add(dv + 128, a3);
    }
}

// ---------------------------------------------------------------------------
extern "C" void kernel_launch(void* const* d_in, const int* in_sizes, int n_in,
                              void* d_out, int out_size) {
    const float* node  = (const float*)d_in[0];
    const float* equiv = (const float*)d_in[1];
    const float* rbf   = (const float*)d_in[2];
    const float* env   = (const float*)d_in[3];
    const float* rij   = (const float*)d_in[4];
    const void*  eidx  = d_in[5];
    const float* Ws    = (const float*)d_in[6];
    const float* bs    = (const float*)d_in[7];
    const float* Wphi  = (const float*)d_in[8];
    const float* bphi  = (const float*)d_in[9];
    const float* Ww    = (const float*)d_in[10];
    const float* bw    = (const float*)d_in[11];

    int n_nodes = in_sizes[0] / U;
    int n_edges = in_sizes[3];

    float* out_ds = (float*)d_out;
    float* out_dv = out_ds + (size_t)n_nodes * U;

    int nb_scan = (n_nodes + 1023) / 1024;

    detect_idx_kernel<<<1, 256>>>((const int*)eidx, n_edges);
    zero_cnt_kernel<<<(n_nodes + 255) / 256, 256>>>(n_nodes);
    zero_out_kernel<<<592, 256>>>((float*)d_out, (long long)out_size);

    cudaFuncSetAttribute(mlp_kernel, cudaFuncAttributeMaxDynamicSharedMemorySize, SMEM_MLP);
    mlp_kernel<<<(n_nodes + MT - 1) / MT, 256, SMEM_MLP>>>(node, Ws, bs, Wphi, bphi, n_nodes);

    hist_kernel<<<400, 256>>>(eidx, n_edges);
    scan1_kernel<<<nb_scan, 1024>>>(n_nodes);
    scan2_kernel<<<1, 64>>>(nb_scan);
    scan3_kernel<<<(n_nodes + 1023) / 1024, 1024>>>(n_nodes);
    scatter_kernel<<<400, 256>>>(eidx, rbf, env, rij, n_edges);

    sweep_kernel<<<NGRP / 2, 128>>>(Ww, bw, equiv, out_ds, out_dv, n_edges);
}